// round 5
// baseline (speedup 1.0000x reference)
#include <cuda_runtime.h>
#include <cuda_fp16.h>

#define N_NODES 100000
#define N_EDGES 3200000
#define N_GRAPHS 4096
#define IN_DIM 128
#define HID 64
#define EPS 1e-5f

#define SCAN_B 512
#define NBLK ((N_NODES + SCAN_B - 1) / SCAN_B)   // 196

// ---------------- scratch (device globals; no allocation) ----------------
__device__ __half2 d_gh [N_NODES * 32];   // fp16 messages
__device__ float   d_acc[N_NODES * HID];  // conv output y (fp32)
__device__ int     d_deg [N_NODES];
__device__ float   d_dinv[N_NODES];
__device__ int     d_off [N_NODES];
__device__ int     d_cur [N_NODES];
__device__ int     d_bsum[NBLK];
__device__ int     d_csr [N_EDGES];
__device__ float   d_stat[4 * 2 * HID];
__device__ float   d_pool[N_GRAPHS * HID];
__device__ float   d_pcnt[N_GRAPHS];
__device__ float   d_q   [N_GRAPHS * HID];

__device__ __forceinline__ void red_add_v4(float* addr, float4 v) {
    unsigned long long p = (unsigned long long)__cvta_generic_to_global(addr);
    asm volatile("red.global.add.v4.f32 [%0], {%1,%2,%3,%4};"
                 :: "l"(p), "f"(v.x), "f"(v.y), "f"(v.z), "f"(v.w) : "memory");
}

__device__ __forceinline__ void bn_to_smem(int L, const float* g, const float* be,
                                           float cnt, float* sS, float* sT) {
    if (threadIdx.x < 64) {
        int f = threadIdx.x;
        float mean = d_stat[L * 128 + f] / cnt;
        float var  = d_stat[L * 128 + 64 + f] / cnt - mean * mean;
        var = fmaxf(var, 0.f);
        float s = g[f] * rsqrtf(var + EPS);
        sS[f] = s;
        sT[f] = be[f] - mean * s;
    }
    __syncthreads();
}

// ---------------- setup kernels ----------------
__global__ void k_initdeg() {
    int i = blockIdx.x * blockDim.x + threadIdx.x;
    if (i < N_NODES) d_deg[i] = 1;                // self loop
}

// zeroing of stats/pool (runs on side stream, off critical path)
__global__ void k_zero() {
    int idx = blockIdx.x * blockDim.x + threadIdx.x;
    int stride = gridDim.x * blockDim.x;
    for (int i = idx; i < 4 * 2 * HID; i += stride) d_stat[i] = 0.f;
    for (int i = idx; i < N_GRAPHS * HID; i += stride) d_pool[i] = 0.f;
    for (int i = idx; i < N_GRAPHS; i += stride) d_pcnt[i] = 0.f;
}

__global__ void k_deg(const int4* __restrict__ col4) {
    int idx = blockIdx.x * blockDim.x + threadIdx.x;
    int stride = gridDim.x * blockDim.x;
    for (int e = idx; e < N_EDGES / 4; e += stride) {
        int4 c = col4[e];
        atomicAdd(&d_deg[c.x], 1);
        atomicAdd(&d_deg[c.y], 1);
        atomicAdd(&d_deg[c.z], 1);
        atomicAdd(&d_deg[c.w], 1);
    }
}

__global__ void k_scanA() {
    __shared__ int s[SCAN_B];
    int i = blockIdx.x * SCAN_B + threadIdx.x;
    int v = (i < N_NODES) ? d_deg[i] - 1 : 0;
    s[threadIdx.x] = v;
    __syncthreads();
    for (int off = 1; off < SCAN_B; off <<= 1) {
        int t = (threadIdx.x >= off) ? s[threadIdx.x - off] : 0;
        __syncthreads();
        s[threadIdx.x] += t;
        __syncthreads();
    }
    if (i < N_NODES) d_off[i] = s[threadIdx.x] - v;
    if (threadIdx.x == SCAN_B - 1) d_bsum[blockIdx.x] = s[SCAN_B - 1];
}

// fused scanB+scanC+dinv: each 256-node block re-reduces the <=196 block sums
__global__ void k_scanC2() {
    __shared__ int sred[256];
    int sb = blockIdx.x >> 1;                 // scan-block index for this block's nodes
    int v = (threadIdx.x < sb) ? d_bsum[threadIdx.x] : 0;
    sred[threadIdx.x] = v;
    __syncthreads();
#pragma unroll
    for (int off = 128; off > 0; off >>= 1) {
        if (threadIdx.x < off) sred[threadIdx.x] += sred[threadIdx.x + off];
        __syncthreads();
    }
    int pref = sred[0];
    int i = blockIdx.x * 256 + threadIdx.x;
    if (i < N_NODES) {
        int o = d_off[i] + pref;
        d_off[i] = o;
        d_cur[i] = o;
        d_dinv[i] = rsqrtf((float)d_deg[i]);
    }
}

__global__ void k_fill(const int4* __restrict__ row4, const int4* __restrict__ col4) {
    int idx = blockIdx.x * blockDim.x + threadIdx.x;
    int stride = gridDim.x * blockDim.x;
    for (int e = idx; e < N_EDGES / 4; e += stride) {
        int4 r = row4[e];
        int4 c = col4[e];
        d_csr[atomicAdd(&d_cur[c.x], 1)] = r.x;
        d_csr[atomicAdd(&d_cur[c.y], 1)] = r.y;
        d_csr[atomicAdd(&d_cur[c.z], 1)] = r.z;
        d_csr[atomicAdd(&d_cur[c.w], 1)] = r.w;
    }
}

// ---------------- GEMM ----------------
template <int KT, bool TRANS, bool DINV>
__global__ void k_gemm(const float* __restrict__ in, const float* __restrict__ W,
                       int stL, const float* __restrict__ g, const float* __restrict__ be,
                       float cnt) {
    __shared__ float sW[64 * 64];
    __shared__ float sX[64 * 68];
    __shared__ float sS[64], sT[64];
    const int tr = threadIdx.x & 15;
    const int tc = threadIdx.x >> 4;
    const int base = blockIdx.x * 64;

    if (TRANS) bn_to_smem(stL, g, be, cnt, sS, sT);

    float acc[4][4];
#pragma unroll
    for (int i = 0; i < 4; i++)
#pragma unroll
        for (int j = 0; j < 4; j++) acc[i][j] = 0.f;

    for (int kt = 0; kt < KT; kt++) {
        for (int i = threadIdx.x; i < 4096; i += 256)
            sW[i] = W[kt * 4096 + i];
        for (int i = threadIdx.x; i < 4096; i += 256) {
            int n = i >> 6, k = i & 63;
            int ng = base + n;
            float v = 0.f;
            if (ng < N_NODES) {
                if (TRANS) v = fmaxf(fmaf(d_acc[ng * 64 + k], sS[k], sT[k]), 0.f);
                else       v = in[ng * (KT * 64) + kt * 64 + k];
            }
            sX[k * 68 + n] = v;
        }
        __syncthreads();
#pragma unroll 8
        for (int kk = 0; kk < 64; kk++) {
            float4 xv = *reinterpret_cast<float4*>(&sX[kk * 68 + tr * 4]);
            float4 wv = *reinterpret_cast<float4*>(&sW[kk * 64 + tc * 4]);
            acc[0][0] = fmaf(xv.x, wv.x, acc[0][0]);
            acc[0][1] = fmaf(xv.x, wv.y, acc[0][1]);
            acc[0][2] = fmaf(xv.x, wv.z, acc[0][2]);
            acc[0][3] = fmaf(xv.x, wv.w, acc[0][3]);
            acc[1][0] = fmaf(xv.y, wv.x, acc[1][0]);
            acc[1][1] = fmaf(xv.y, wv.y, acc[1][1]);
            acc[1][2] = fmaf(xv.y, wv.z, acc[1][2]);
            acc[1][3] = fmaf(xv.y, wv.w, acc[1][3]);
            acc[2][0] = fmaf(xv.z, wv.x, acc[2][0]);
            acc[2][1] = fmaf(xv.z, wv.y, acc[2][1]);
            acc[2][2] = fmaf(xv.z, wv.z, acc[2][2]);
            acc[2][3] = fmaf(xv.z, wv.w, acc[2][3]);
            acc[3][0] = fmaf(xv.w, wv.x, acc[3][0]);
            acc[3][1] = fmaf(xv.w, wv.y, acc[3][1]);
            acc[3][2] = fmaf(xv.w, wv.z, acc[3][2]);
            acc[3][3] = fmaf(xv.w, wv.w, acc[3][3]);
        }
        __syncthreads();
    }
#pragma unroll
    for (int i = 0; i < 4; i++) {
        int n = base + tr * 4 + i;
        if (n < N_NODES) {
            float dv = DINV ? d_dinv[n] : 1.0f;
            __half2 h0 = __floats2half2_rn(acc[i][0] * dv, acc[i][1] * dv);
            __half2 h1 = __floats2half2_rn(acc[i][2] * dv, acc[i][3] * dv);
            uint2 u;
            u.x = *reinterpret_cast<unsigned*>(&h0);
            u.y = *reinterpret_cast<unsigned*>(&h1);
            *reinterpret_cast<uint2*>(&d_gh[n * 32 + tc * 2]) = u;
        }
    }
}

// ---------------- CSR gather-aggregate + fused BN stats ---------------------
template <bool ROWDINV>
__global__ void k_aggr2(int L) {
    __shared__ float ssum[16 * 65];
    __shared__ float ssq [16 * 65];
    int w = threadIdx.x >> 5;
    int lane = threadIdx.x & 31;
    int node = blockIdx.x * 16 + w;

    float2 y = {0.f, 0.f};
    if (node < N_NODES) {
        int start = d_off[node];
        int deg = d_deg[node] - 1;
        float2 a0={0,0},a1={0,0},a2={0,0},a3={0,0},a4={0,0},a5={0,0},a6={0,0},a7={0,0};
        float2 self = __half22float2(d_gh[node * 32 + lane]);
        for (int base = 0; base < deg; base += 32) {
            int rem = deg - base; if (rem > 32) rem = 32;
            int id = (lane < rem) ? __ldg(&d_csr[start + base + lane]) : 0;
            float dvl = (ROWDINV && lane < rem) ? __ldg(&d_dinv[id]) : 0.f;
            int j = 0;
            for (; j + 8 <= rem; j += 8) {
                int r0 = __shfl_sync(0xffffffffu, id, j);
                int r1 = __shfl_sync(0xffffffffu, id, j + 1);
                int r2 = __shfl_sync(0xffffffffu, id, j + 2);
                int r3 = __shfl_sync(0xffffffffu, id, j + 3);
                int r4 = __shfl_sync(0xffffffffu, id, j + 4);
                int r5 = __shfl_sync(0xffffffffu, id, j + 5);
                int r6 = __shfl_sync(0xffffffffu, id, j + 6);
                int r7 = __shfl_sync(0xffffffffu, id, j + 7);
                float2 v0 = __half22float2(d_gh[r0 * 32 + lane]);
                float2 v1 = __half22float2(d_gh[r1 * 32 + lane]);
                float2 v2 = __half22float2(d_gh[r2 * 32 + lane]);
                float2 v3 = __half22float2(d_gh[r3 * 32 + lane]);
                float2 v4 = __half22float2(d_gh[r4 * 32 + lane]);
                float2 v5 = __half22float2(d_gh[r5 * 32 + lane]);
                float2 v6 = __half22float2(d_gh[r6 * 32 + lane]);
                float2 v7 = __half22float2(d_gh[r7 * 32 + lane]);
                if (ROWDINV) {
                    float d0 = __shfl_sync(0xffffffffu, dvl, j);
                    float d1 = __shfl_sync(0xffffffffu, dvl, j + 1);
                    float d2 = __shfl_sync(0xffffffffu, dvl, j + 2);
                    float d3 = __shfl_sync(0xffffffffu, dvl, j + 3);
                    float d4 = __shfl_sync(0xffffffffu, dvl, j + 4);
                    float d5 = __shfl_sync(0xffffffffu, dvl, j + 5);
                    float d6 = __shfl_sync(0xffffffffu, dvl, j + 6);
                    float d7 = __shfl_sync(0xffffffffu, dvl, j + 7);
                    a0.x = fmaf(d0, v0.x, a0.x); a0.y = fmaf(d0, v0.y, a0.y);
                    a1.x = fmaf(d1, v1.x, a1.x); a1.y = fmaf(d1, v1.y, a1.y);
                    a2.x = fmaf(d2, v2.x, a2.x); a2.y = fmaf(d2, v2.y, a2.y);
                    a3.x = fmaf(d3, v3.x, a3.x); a3.y = fmaf(d3, v3.y, a3.y);
                    a4.x = fmaf(d4, v4.x, a4.x); a4.y = fmaf(d4, v4.y, a4.y);
                    a5.x = fmaf(d5, v5.x, a5.x); a5.y = fmaf(d5, v5.y, a5.y);
                    a6.x = fmaf(d6, v6.x, a6.x); a6.y = fmaf(d6, v6.y, a6.y);
                    a7.x = fmaf(d7, v7.x, a7.x); a7.y = fmaf(d7, v7.y, a7.y);
                } else {
                    a0.x += v0.x; a0.y += v0.y;
                    a1.x += v1.x; a1.y += v1.y;
                    a2.x += v2.x; a2.y += v2.y;
                    a3.x += v3.x; a3.y += v3.y;
                    a4.x += v4.x; a4.y += v4.y;
                    a5.x += v5.x; a5.y += v5.y;
                    a6.x += v6.x; a6.y += v6.y;
                    a7.x += v7.x; a7.y += v7.y;
                }
            }
            for (; j + 2 <= rem; j += 2) {
                int r0 = __shfl_sync(0xffffffffu, id, j);
                int r1 = __shfl_sync(0xffffffffu, id, j + 1);
                float2 v0 = __half22float2(d_gh[r0 * 32 + lane]);
                float2 v1 = __half22float2(d_gh[r1 * 32 + lane]);
                if (ROWDINV) {
                    float d0 = __shfl_sync(0xffffffffu, dvl, j);
                    float d1 = __shfl_sync(0xffffffffu, dvl, j + 1);
                    a0.x = fmaf(d0, v0.x, a0.x); a0.y = fmaf(d0, v0.y, a0.y);
                    a1.x = fmaf(d1, v1.x, a1.x); a1.y = fmaf(d1, v1.y, a1.y);
                } else {
                    a0.x += v0.x; a0.y += v0.y;
                    a1.x += v1.x; a1.y += v1.y;
                }
            }
            if (j < rem) {
                int r = __shfl_sync(0xffffffffu, id, j);
                float2 v = __half22float2(d_gh[r * 32 + lane]);
                if (ROWDINV) {
                    float dr = __shfl_sync(0xffffffffu, dvl, j);
                    a0.x = fmaf(dr, v.x, a0.x); a0.y = fmaf(dr, v.y, a0.y);
                } else {
                    a0.x += v.x; a0.y += v.y;
                }
            }
        }
        float dv = d_dinv[node];
        float selfs = ROWDINV ? dv : 1.0f;
        y.x = (((a0.x + a1.x) + (a2.x + a3.x)) + ((a4.x + a5.x) + (a6.x + a7.x)) + selfs * self.x) * dv;
        y.y = (((a0.y + a1.y) + (a2.y + a3.y)) + ((a4.y + a5.y) + (a6.y + a7.y)) + selfs * self.y) * dv;
        reinterpret_cast<float2*>(d_acc)[node * 32 + lane] = y;
    }

    ssum[w * 65 + 2 * lane]     = y.x;
    ssum[w * 65 + 2 * lane + 1] = y.y;
    ssq [w * 65 + 2 * lane]     = y.x * y.x;
    ssq [w * 65 + 2 * lane + 1] = y.y * y.y;
    __syncthreads();
    if (threadIdx.x < 128) {
        int feat = threadIdx.x & 63;
        bool isq = threadIdx.x >= 64;
        const float* src = isq ? ssq : ssum;
        float acc = 0.f;
#pragma unroll
        for (int ww = 0; ww < 16; ww++) acc += src[ww * 65 + feat];
        atomicAdd(&d_stat[L * 128 + (isq ? 64 : 0) + feat], acc);
    }
}

// ---------------- pooling + head ----------------
__global__ void k_pool(const int* __restrict__ batch,
                       const float* __restrict__ g, const float* __restrict__ be) {
    __shared__ float sS[64], sT[64];
    bn_to_smem(2, g, be, (float)N_NODES, sS, sT);
    int t = blockIdx.x * blockDim.x + threadIdx.x;
    int lane = t & 15;
    int n = t >> 4;
    if (n >= N_NODES) return;
    int b = batch[n];
    float4 a = *reinterpret_cast<const float4*>(&d_acc[n * 64 + lane * 4]);
    float4 z;
    z.x = fmaxf(fmaf(a.x, sS[lane * 4 + 0], sT[lane * 4 + 0]), 0.f);
    z.y = fmaxf(fmaf(a.y, sS[lane * 4 + 1], sT[lane * 4 + 1]), 0.f);
    z.z = fmaxf(fmaf(a.z, sS[lane * 4 + 2], sT[lane * 4 + 2]), 0.f);
    z.w = fmaxf(fmaf(a.w, sS[lane * 4 + 3], sT[lane * 4 + 3]), 0.f);
    red_add_v4(&d_pool[b * 64 + lane * 4], z);
    if (lane == 0) atomicAdd(&d_pcnt[b], 1.0f);
}

__global__ void k_fc1(const float* __restrict__ W1) {
    __shared__ float sp[64];
    int gidx = blockIdx.x, f = threadIdx.x;
    float cnt = fmaxf(d_pcnt[gidx], 1.f);
    sp[f] = d_pool[gidx * 64 + f] / cnt;
    __syncthreads();
    float q = 0.f;
#pragma unroll 8
    for (int k = 0; k < 64; k++)
        q = fmaf(sp[k], __ldg(&W1[k * 64 + f]), q);
    d_q[gidx * 64 + f] = q;
    atomicAdd(&d_stat[3 * 128 + f], q);
    atomicAdd(&d_stat[3 * 128 + 64 + f], q * q);
}

__global__ void k_fc2(const float* __restrict__ W2, const float* __restrict__ b2,
                      const float* __restrict__ gf, const float* __restrict__ bf,
                      float* __restrict__ out) {
    __shared__ float sS[64], sT[64];
    bn_to_smem(3, gf, bf, (float)N_GRAPHS, sS, sT);
    int g = blockIdx.x * (blockDim.x / 32) + (threadIdx.x >> 5);
    int lane = threadIdx.x & 31;
    if (g >= N_GRAPHS) return;
    float acc = 0.f;
#pragma unroll
    for (int j = 0; j < 2; j++) {
        int f = lane + 32 * j;
        float z = fmaxf(fmaf(d_q[g * 64 + f], sS[f], sT[f]), 0.f);
        acc = fmaf(z, W2[f], acc);
    }
#pragma unroll
    for (int o = 16; o > 0; o >>= 1)
        acc += __shfl_down_sync(0xffffffffu, acc, o);
    if (lane == 0) out[g] = acc + b2[0];
}

// ---------------- launch ----------------
extern "C" void kernel_launch(void* const* d_in, const int* in_sizes, int n_in,
                              void* d_out, int out_size) {
    const float* x     = (const float*)d_in[0];
    const int*   ei    = (const int*)d_in[1];
    const int*   row   = ei;
    const int*   col   = ei + N_EDGES;
    const int*   batch = (const int*)d_in[2];
    const float* Wc0 = (const float*)d_in[3];
    const float* g0  = (const float*)d_in[5];
    const float* be0 = (const float*)d_in[6];
    const float* Wc1 = (const float*)d_in[7];
    const float* g1  = (const float*)d_in[9];
    const float* be1 = (const float*)d_in[10];
    const float* Wc2 = (const float*)d_in[11];
    const float* g2  = (const float*)d_in[13];
    const float* be2 = (const float*)d_in[14];
    const float* W1  = (const float*)d_in[15];
    const float* gf  = (const float*)d_in[17];
    const float* bf  = (const float*)d_in[18];
    const float* W2  = (const float*)d_in[19];
    const float* b2  = (const float*)d_in[20];
    float* out = (float*)d_out;

    static cudaStream_t s1 = nullptr;
    static cudaEvent_t eFork = nullptr, eGemm0 = nullptr;
    if (s1 == nullptr) {
        cudaStreamCreateWithFlags(&s1, cudaStreamNonBlocking);
        cudaEventCreateWithFlags(&eFork, cudaEventDisableTiming);
        cudaEventCreateWithFlags(&eGemm0, cudaEventDisableTiming);
    }

    const int GEMM_GRID = (N_NODES + 63) / 64;              // 1563
    const int AGGR_GRID = (N_NODES + 15) / 16;              // 6250 (512 thr)
    const int POOL_GRID = (N_NODES * 16 + 255) / 256;       // 6250
    const int N256 = (N_NODES + 255) / 256;                 // 391

    // Side stream: zero stats/pool, then GEMM0 (x@Wc0, no graph dependency)
    cudaEventRecord(eFork, 0);
    cudaStreamWaitEvent(s1, eFork, 0);
    k_zero<<<512, 256, 0, s1>>>();
    k_gemm<2, false, false><<<GEMM_GRID, 256, 0, s1>>>(x, Wc0, 0, nullptr, nullptr, 1.f);
    cudaEventRecord(eGemm0, s1);

    // Critical path: CSR build
    k_initdeg<<<N256, 256>>>();
    k_deg <<<4096, 256>>>((const int4*)col);
    k_scanA<<<NBLK, SCAN_B>>>();
    k_scanC2<<<N256, 256>>>();
    k_fill<<<4096, 256>>>((const int4*)row, (const int4*)col);

    cudaStreamWaitEvent(0, eGemm0, 0);

    // layer 0 (gh = raw h fp16; dinv[row] applied in gather)
    k_aggr2<true><<<AGGR_GRID, 512>>>(0);

    // layer 1
    k_gemm<1, true, true><<<GEMM_GRID, 256>>>(x, Wc1, 0, g0, be0, (float)N_NODES);
    k_aggr2<false><<<AGGR_GRID, 512>>>(1);

    // layer 2
    k_gemm<1, true, true><<<GEMM_GRID, 256>>>(x, Wc2, 1, g1, be1, (float)N_NODES);
    k_aggr2<false><<<AGGR_GRID, 512>>>(2);

    // pooling + head
    k_pool<<<POOL_GRID, 256>>>(batch, g2, be2);
    k_fc1<<<N_GRAPHS, 64>>>(W1);
    k_fc2<<<N_GRAPHS / 8, 256>>>(W2, b2, gf, bf, out);
}

// round 6
// speedup vs baseline: 1.1566x; 1.1566x over previous
#include <cuda_runtime.h>
#include <cuda_fp16.h>

#define N_NODES 100000
#define N_EDGES 3200000
#define N_GRAPHS 4096
#define IN_DIM 128
#define HID 64
#define EPS 1e-5f

#define SCAN_B 512
#define NBLK ((N_NODES + SCAN_B - 1) / SCAN_B)   // 196

// ---------------- scratch (device globals; no allocation) ----------------
__device__ __half2 d_gh [N_NODES * 32];   // fp16 messages, 128B per node row
__device__ float   d_acc[N_NODES * HID];  // conv output y (fp32)
__device__ int     d_deg [N_NODES];
__device__ float   d_dinv[N_NODES];
__device__ int     d_off [N_NODES];
__device__ int     d_cur [N_NODES];
__device__ int     d_bsum[NBLK];
__device__ int     d_csr [N_EDGES];
__device__ float   d_stat[4 * 2 * HID];
__device__ float   d_pool[N_GRAPHS * HID];
__device__ float   d_pcnt[N_GRAPHS];
__device__ float   d_q   [N_GRAPHS * HID];

__device__ __forceinline__ void red_add_v4(float* addr, float4 v) {
    unsigned long long p = (unsigned long long)__cvta_generic_to_global(addr);
    asm volatile("red.global.add.v4.f32 [%0], {%1,%2,%3,%4};"
                 :: "l"(p), "f"(v.x), "f"(v.y), "f"(v.z), "f"(v.w) : "memory");
}

__device__ __forceinline__ void bn_to_smem(int L, const float* g, const float* be,
                                           float cnt, float* sS, float* sT) {
    if (threadIdx.x < 64) {
        int f = threadIdx.x;
        float mean = d_stat[L * 128 + f] / cnt;
        float var  = d_stat[L * 128 + 64 + f] / cnt - mean * mean;
        var = fmaxf(var, 0.f);
        float s = g[f] * rsqrtf(var + EPS);
        sS[f] = s;
        sT[f] = be[f] - mean * s;
    }
    __syncthreads();
}

// ---------------- setup kernels ----------------
__global__ void k_initdeg() {
    int i = blockIdx.x * blockDim.x + threadIdx.x;
    if (i < N_NODES) d_deg[i] = 1;                // self loop
}

__global__ void k_zero() {
    int idx = blockIdx.x * blockDim.x + threadIdx.x;
    int stride = gridDim.x * blockDim.x;
    for (int i = idx; i < 4 * 2 * HID; i += stride) d_stat[i] = 0.f;
    for (int i = idx; i < N_GRAPHS * HID; i += stride) d_pool[i] = 0.f;
    for (int i = idx; i < N_GRAPHS; i += stride) d_pcnt[i] = 0.f;
}

__global__ void k_deg(const int* __restrict__ col) {
    int idx = blockIdx.x * blockDim.x + threadIdx.x;
    int stride = gridDim.x * blockDim.x;
    for (int e = idx; e < N_EDGES; e += stride)
        atomicAdd(&d_deg[col[e]], 1);
}

__global__ void k_scanA() {
    __shared__ int s[SCAN_B];
    int i = blockIdx.x * SCAN_B + threadIdx.x;
    int v = (i < N_NODES) ? d_deg[i] - 1 : 0;
    s[threadIdx.x] = v;
    __syncthreads();
    for (int off = 1; off < SCAN_B; off <<= 1) {
        int t = (threadIdx.x >= off) ? s[threadIdx.x - off] : 0;
        __syncthreads();
        s[threadIdx.x] += t;
        __syncthreads();
    }
    if (i < N_NODES) d_off[i] = s[threadIdx.x] - v;
    if (threadIdx.x == SCAN_B - 1) d_bsum[blockIdx.x] = s[SCAN_B - 1];
}

// fused scanB+scanC+dinv
__global__ void k_scanC2() {
    __shared__ int sred[256];
    int sb = blockIdx.x >> 1;
    int v = (threadIdx.x < sb) ? d_bsum[threadIdx.x] : 0;
    sred[threadIdx.x] = v;
    __syncthreads();
#pragma unroll
    for (int off = 128; off > 0; off >>= 1) {
        if (threadIdx.x < off) sred[threadIdx.x] += sred[threadIdx.x + off];
        __syncthreads();
    }
    int pref = sred[0];
    int i = blockIdx.x * 256 + threadIdx.x;
    if (i < N_NODES) {
        int o = d_off[i] + pref;
        d_off[i] = o;
        d_cur[i] = o;
        d_dinv[i] = rsqrtf((float)d_deg[i]);
    }
}

__global__ void k_fill(const int* __restrict__ row, const int* __restrict__ col) {
    int idx = blockIdx.x * blockDim.x + threadIdx.x;
    int stride = gridDim.x * blockDim.x;
    for (int e = idx; e < N_EDGES; e += stride) {
        int pos = atomicAdd(&d_cur[col[e]], 1);
        d_csr[pos] = row[e];
    }
}

// ---------------- GEMM ----------------
template <int KT, bool TRANS, bool DINV>
__global__ void k_gemm(const float* __restrict__ in, const float* __restrict__ W,
                       int stL, const float* __restrict__ g, const float* __restrict__ be,
                       float cnt) {
    __shared__ float sW[64 * 64];
    __shared__ float sX[64 * 68];
    __shared__ float sS[64], sT[64];
    const int tr = threadIdx.x & 15;
    const int tc = threadIdx.x >> 4;
    const int base = blockIdx.x * 64;

    if (TRANS) bn_to_smem(stL, g, be, cnt, sS, sT);

    float acc[4][4];
#pragma unroll
    for (int i = 0; i < 4; i++)
#pragma unroll
        for (int j = 0; j < 4; j++) acc[i][j] = 0.f;

    for (int kt = 0; kt < KT; kt++) {
        for (int i = threadIdx.x; i < 4096; i += 256)
            sW[i] = W[kt * 4096 + i];
        for (int i = threadIdx.x; i < 4096; i += 256) {
            int n = i >> 6, k = i & 63;
            int ng = base + n;
            float v = 0.f;
            if (ng < N_NODES) {
                if (TRANS) v = fmaxf(fmaf(d_acc[ng * 64 + k], sS[k], sT[k]), 0.f);
                else       v = in[ng * (KT * 64) + kt * 64 + k];
            }
            sX[k * 68 + n] = v;
        }
        __syncthreads();
#pragma unroll 8
        for (int kk = 0; kk < 64; kk++) {
            float4 xv = *reinterpret_cast<float4*>(&sX[kk * 68 + tr * 4]);
            float4 wv = *reinterpret_cast<float4*>(&sW[kk * 64 + tc * 4]);
            acc[0][0] = fmaf(xv.x, wv.x, acc[0][0]);
            acc[0][1] = fmaf(xv.x, wv.y, acc[0][1]);
            acc[0][2] = fmaf(xv.x, wv.z, acc[0][2]);
            acc[0][3] = fmaf(xv.x, wv.w, acc[0][3]);
            acc[1][0] = fmaf(xv.y, wv.x, acc[1][0]);
            acc[1][1] = fmaf(xv.y, wv.y, acc[1][1]);
            acc[1][2] = fmaf(xv.y, wv.z, acc[1][2]);
            acc[1][3] = fmaf(xv.y, wv.w, acc[1][3]);
            acc[2][0] = fmaf(xv.z, wv.x, acc[2][0]);
            acc[2][1] = fmaf(xv.z, wv.y, acc[2][1]);
            acc[2][2] = fmaf(xv.z, wv.z, acc[2][2]);
            acc[2][3] = fmaf(xv.z, wv.w, acc[2][3]);
            acc[3][0] = fmaf(xv.w, wv.x, acc[3][0]);
            acc[3][1] = fmaf(xv.w, wv.y, acc[3][1]);
            acc[3][2] = fmaf(xv.w, wv.z, acc[3][2]);
            acc[3][3] = fmaf(xv.w, wv.w, acc[3][3]);
        }
        __syncthreads();
    }
#pragma unroll
    for (int i = 0; i < 4; i++) {
        int n = base + tr * 4 + i;
        if (n < N_NODES) {
            float dv = DINV ? d_dinv[n] : 1.0f;
            __half2 h0 = __floats2half2_rn(acc[i][0] * dv, acc[i][1] * dv);
            __half2 h1 = __floats2half2_rn(acc[i][2] * dv, acc[i][3] * dv);
            uint2 u;
            u.x = *reinterpret_cast<unsigned*>(&h0);
            u.y = *reinterpret_cast<unsigned*>(&h1);
            *reinterpret_cast<uint2*>(&d_gh[n * 32 + tc * 2]) = u;
        }
    }
}

// ---------------- CSR gather-aggregate (4 messages / warp-step) -------------
// Lane groups of 8: group g handles message j+g; each group reads one full
// 128B message row as uint4 (LDG.128). 8 fp32 accumulators/lane; cross-group
// shfl_xor reduction at the end. Fused BN stats.
template <bool ROWDINV>
__global__ void k_aggr3(int L) {
    __shared__ float ssum[16 * 65];
    __shared__ float ssq [16 * 65];
    const int w = threadIdx.x >> 5;
    const int lane = threadIdx.x & 31;
    const int grp = lane >> 3;          // 0..3 message slot
    const int sub = lane & 7;           // 16B chunk within row
    const int node = blockIdx.x * 16 + w;
    const uint4* gh4 = reinterpret_cast<const uint4*>(d_gh);   // 8 uint4 per row

    float acc[8];
#pragma unroll
    for (int i = 0; i < 8; i++) acc[i] = 0.f;

    if (node < N_NODES) {
        int start = d_off[node];
        int deg = d_deg[node] - 1;
        for (int base = 0; base < deg; base += 32) {
            int rem = deg - base; if (rem > 32) rem = 32;
            int id = (lane < rem) ? __ldg(&d_csr[start + base + lane]) : 0;
            float dvl = 0.f;
            if (ROWDINV) dvl = (lane < rem) ? __ldg(&d_dinv[id]) : 0.f;
            for (int j = 0; j < rem; j += 4) {
                int src = j + grp;
                bool ok = src < rem;
                int r = __shfl_sync(0xffffffffu, id, src & 31);
                float dm = 1.f;
                if (ROWDINV) dm = __shfl_sync(0xffffffffu, dvl, src & 31);
                if (ok) {
                    uint4 u = __ldg(&gh4[r * 8 + sub]);
                    __half2 h0 = *reinterpret_cast<__half2*>(&u.x);
                    __half2 h1 = *reinterpret_cast<__half2*>(&u.y);
                    __half2 h2 = *reinterpret_cast<__half2*>(&u.z);
                    __half2 h3 = *reinterpret_cast<__half2*>(&u.w);
                    float2 f0 = __half22float2(h0);
                    float2 f1 = __half22float2(h1);
                    float2 f2 = __half22float2(h2);
                    float2 f3 = __half22float2(h3);
                    if (ROWDINV) {
                        acc[0] = fmaf(dm, f0.x, acc[0]); acc[1] = fmaf(dm, f0.y, acc[1]);
                        acc[2] = fmaf(dm, f1.x, acc[2]); acc[3] = fmaf(dm, f1.y, acc[3]);
                        acc[4] = fmaf(dm, f2.x, acc[4]); acc[5] = fmaf(dm, f2.y, acc[5]);
                        acc[6] = fmaf(dm, f3.x, acc[6]); acc[7] = fmaf(dm, f3.y, acc[7]);
                    } else {
                        acc[0] += f0.x; acc[1] += f0.y;
                        acc[2] += f1.x; acc[3] += f1.y;
                        acc[4] += f2.x; acc[5] += f2.y;
                        acc[6] += f3.x; acc[7] += f3.y;
                    }
                }
            }
        }
        // self loop (group 0 only; reduction will propagate it)
        if (grp == 0) {
            float selfs = ROWDINV ? d_dinv[node] : 1.f;
            uint4 su = gh4[node * 8 + sub];
            __half2 h0 = *reinterpret_cast<__half2*>(&su.x);
            __half2 h1 = *reinterpret_cast<__half2*>(&su.y);
            __half2 h2 = *reinterpret_cast<__half2*>(&su.z);
            __half2 h3 = *reinterpret_cast<__half2*>(&su.w);
            float2 f0 = __half22float2(h0);
            float2 f1 = __half22float2(h1);
            float2 f2 = __half22float2(h2);
            float2 f3 = __half22float2(h3);
            acc[0] = fmaf(selfs, f0.x, acc[0]); acc[1] = fmaf(selfs, f0.y, acc[1]);
            acc[2] = fmaf(selfs, f1.x, acc[2]); acc[3] = fmaf(selfs, f1.y, acc[3]);
            acc[4] = fmaf(selfs, f2.x, acc[4]); acc[5] = fmaf(selfs, f2.y, acc[5]);
            acc[6] = fmaf(selfs, f3.x, acc[6]); acc[7] = fmaf(selfs, f3.y, acc[7]);
        }
    }

    // reduce across the 4 lane groups (whole warp participates)
#pragma unroll
    for (int i = 0; i < 8; i++) acc[i] += __shfl_xor_sync(0xffffffffu, acc[i], 8);
#pragma unroll
    for (int i = 0; i < 8; i++) acc[i] += __shfl_xor_sync(0xffffffffu, acc[i], 16);

    float dv = (node < N_NODES) ? d_dinv[node] : 0.f;
#pragma unroll
    for (int i = 0; i < 8; i++) acc[i] *= dv;

    if (grp == 0) {
        if (node < N_NODES) {
            float4 o0 = make_float4(acc[0], acc[1], acc[2], acc[3]);
            float4 o1 = make_float4(acc[4], acc[5], acc[6], acc[7]);
            *reinterpret_cast<float4*>(&d_acc[node * 64 + sub * 8])     = o0;
            *reinterpret_cast<float4*>(&d_acc[node * 64 + sub * 8 + 4]) = o1;
        }
#pragma unroll
        for (int i = 0; i < 8; i++) {
            ssum[w * 65 + sub * 8 + i] = acc[i];
            ssq [w * 65 + sub * 8 + i] = acc[i] * acc[i];
        }
    }
    __syncthreads();
    if (threadIdx.x < 128) {
        int feat = threadIdx.x & 63;
        bool isq = threadIdx.x >= 64;
        const float* src = isq ? ssq : ssum;
        float a = 0.f;
#pragma unroll
        for (int ww = 0; ww < 16; ww++) a += src[ww * 65 + feat];
        atomicAdd(&d_stat[L * 128 + (isq ? 64 : 0) + feat], a);
    }
}

// ---------------- pooling + head ----------------
__global__ void k_pool(const int* __restrict__ batch,
                       const float* __restrict__ g, const float* __restrict__ be) {
    __shared__ float sS[64], sT[64];
    bn_to_smem(2, g, be, (float)N_NODES, sS, sT);
    int t = blockIdx.x * blockDim.x + threadIdx.x;
    int lane = t & 15;
    int n = t >> 4;
    if (n >= N_NODES) return;
    int b = batch[n];
    float4 a = *reinterpret_cast<const float4*>(&d_acc[n * 64 + lane * 4]);
    float4 z;
    z.x = fmaxf(fmaf(a.x, sS[lane * 4 + 0], sT[lane * 4 + 0]), 0.f);
    z.y = fmaxf(fmaf(a.y, sS[lane * 4 + 1], sT[lane * 4 + 1]), 0.f);
    z.z = fmaxf(fmaf(a.z, sS[lane * 4 + 2], sT[lane * 4 + 2]), 0.f);
    z.w = fmaxf(fmaf(a.w, sS[lane * 4 + 3], sT[lane * 4 + 3]), 0.f);
    red_add_v4(&d_pool[b * 64 + lane * 4], z);
    if (lane == 0) atomicAdd(&d_pcnt[b], 1.0f);
}

__global__ void k_fc1(const float* __restrict__ W1) {
    __shared__ float sp[64];
    int gidx = blockIdx.x, f = threadIdx.x;
    float cnt = fmaxf(d_pcnt[gidx], 1.f);
    sp[f] = d_pool[gidx * 64 + f] / cnt;
    __syncthreads();
    float q = 0.f;
#pragma unroll 8
    for (int k = 0; k < 64; k++)
        q = fmaf(sp[k], __ldg(&W1[k * 64 + f]), q);
    d_q[gidx * 64 + f] = q;
    atomicAdd(&d_stat[3 * 128 + f], q);
    atomicAdd(&d_stat[3 * 128 + 64 + f], q * q);
}

__global__ void k_fc2(const float* __restrict__ W2, const float* __restrict__ b2,
                      const float* __restrict__ gf, const float* __restrict__ bf,
                      float* __restrict__ out) {
    __shared__ float sS[64], sT[64];
    bn_to_smem(3, gf, bf, (float)N_GRAPHS, sS, sT);
    int g = blockIdx.x * (blockDim.x / 32) + (threadIdx.x >> 5);
    int lane = threadIdx.x & 31;
    if (g >= N_GRAPHS) return;
    float acc = 0.f;
#pragma unroll
    for (int j = 0; j < 2; j++) {
        int f = lane + 32 * j;
        float z = fmaxf(fmaf(d_q[g * 64 + f], sS[f], sT[f]), 0.f);
        acc = fmaf(z, W2[f], acc);
    }
#pragma unroll
    for (int o = 16; o > 0; o >>= 1)
        acc += __shfl_down_sync(0xffffffffu, acc, o);
    if (lane == 0) out[g] = acc + b2[0];
}

// ---------------- launch ----------------
extern "C" void kernel_launch(void* const* d_in, const int* in_sizes, int n_in,
                              void* d_out, int out_size) {
    const float* x     = (const float*)d_in[0];
    const int*   ei    = (const int*)d_in[1];
    const int*   row   = ei;
    const int*   col   = ei + N_EDGES;
    const int*   batch = (const int*)d_in[2];
    const float* Wc0 = (const float*)d_in[3];
    const float* g0  = (const float*)d_in[5];
    const float* be0 = (const float*)d_in[6];
    const float* Wc1 = (const float*)d_in[7];
    const float* g1  = (const float*)d_in[9];
    const float* be1 = (const float*)d_in[10];
    const float* Wc2 = (const float*)d_in[11];
    const float* g2  = (const float*)d_in[13];
    const float* be2 = (const float*)d_in[14];
    const float* W1  = (const float*)d_in[15];
    const float* gf  = (const float*)d_in[17];
    const float* bf  = (const float*)d_in[18];
    const float* W2  = (const float*)d_in[19];
    const float* b2  = (const float*)d_in[20];
    float* out = (float*)d_out;

    static cudaStream_t s1 = nullptr;
    static cudaEvent_t eFork = nullptr, eGemm0 = nullptr;
    if (s1 == nullptr) {
        cudaStreamCreateWithFlags(&s1, cudaStreamNonBlocking);
        cudaEventCreateWithFlags(&eFork, cudaEventDisableTiming);
        cudaEventCreateWithFlags(&eGemm0, cudaEventDisableTiming);
    }

    const int GEMM_GRID = (N_NODES + 63) / 64;              // 1563
    const int AGGR_GRID = (N_NODES + 15) / 16;              // 6250 (512 thr)
    const int POOL_GRID = (N_NODES * 16 + 255) / 256;       // 6250
    const int N256 = (N_NODES + 255) / 256;                 // 391

    // Side stream: zero stats/pool, then GEMM0 (x@Wc0, no graph dependency)
    cudaEventRecord(eFork, 0);
    cudaStreamWaitEvent(s1, eFork, 0);
    k_zero<<<512, 256, 0, s1>>>();
    k_gemm<2, false, false><<<GEMM_GRID, 256, 0, s1>>>(x, Wc0, 0, nullptr, nullptr, 1.f);
    cudaEventRecord(eGemm0, s1);

    // Critical path: CSR build (scalar atomics — R4-proven)
    k_initdeg<<<N256, 256>>>();
    k_deg <<<8192, 256>>>(col);
    k_scanA<<<NBLK, SCAN_B>>>();
    k_scanC2<<<N256, 256>>>();
    k_fill<<<8192, 256>>>(row, col);

    cudaStreamWaitEvent(0, eGemm0, 0);

    // layer 0 (gh = raw h fp16; dinv[row] applied in gather)
    k_aggr3<true><<<AGGR_GRID, 512>>>(0);

    // layer 1
    k_gemm<1, true, true><<<GEMM_GRID, 256>>>(x, Wc1, 0, g0, be0, (float)N_NODES);
    k_aggr3<false><<<AGGR_GRID, 512>>>(1);

    // layer 2
    k_gemm<1, true, true><<<GEMM_GRID, 256>>>(x, Wc2, 1, g1, be1, (float)N_NODES);
    k_aggr3<false><<<AGGR_GRID, 512>>>(2);

    // pooling + head
    k_pool<<<POOL_GRID, 256>>>(batch, g2, be2);
    k_fc1<<<N_GRAPHS, 64>>>(W1);
    k_fc2<<<N_GRAPHS / 8, 256>>>(W2, b2, gf, bf, out);
}

// round 7
// speedup vs baseline: 1.1935x; 1.0319x over previous
#include <cuda_runtime.h>
#include <cuda_fp16.h>

#define N_NODES 100000
#define N_EDGES 3200000
#define N_GRAPHS 4096
#define IN_DIM 128
#define HID 64
#define EPS 1e-5f

#define SCAN_B 512
#define NBLK ((N_NODES + SCAN_B - 1) / SCAN_B)   // 196
#define CSR_CAP (N_EDGES + 8 * N_NODES)          // padded CSR capacity

// ---------------- scratch (device globals; no allocation) ----------------
// d_gh has one extra, permanently-zero sentinel row at index N_NODES.
__device__ __half2 d_gh [(N_NODES + 1) * 32];
__device__ float   d_acc[N_NODES * HID];
__device__ int     d_deg [N_NODES];
__device__ float   d_dinv[N_NODES + 1];          // [N_NODES] = 0 sentinel
__device__ int     d_off [N_NODES];
__device__ int     d_cur [N_NODES];
__device__ int     d_bsum[NBLK];
__device__ int     d_csr [CSR_CAP];
__device__ float   d_stat[4 * 2 * HID];
__device__ float   d_pool[N_GRAPHS * HID];
__device__ float   d_pcnt[N_GRAPHS];
__device__ float   d_q   [N_GRAPHS * HID];

__device__ __forceinline__ void red_add_v4(float* addr, float4 v) {
    unsigned long long p = (unsigned long long)__cvta_generic_to_global(addr);
    asm volatile("red.global.add.v4.f32 [%0], {%1,%2,%3,%4};"
                 :: "l"(p), "f"(v.x), "f"(v.y), "f"(v.z), "f"(v.w) : "memory");
}

__device__ __forceinline__ void bn_to_smem(int L, const float* g, const float* be,
                                           float cnt, float* sS, float* sT) {
    if (threadIdx.x < 64) {
        int f = threadIdx.x;
        float mean = d_stat[L * 128 + f] / cnt;
        float var  = d_stat[L * 128 + 64 + f] / cnt - mean * mean;
        var = fmaxf(var, 0.f);
        float s = g[f] * rsqrtf(var + EPS);
        sS[f] = s;
        sT[f] = be[f] - mean * s;
    }
    __syncthreads();
}

// ---------------- setup kernels ----------------
__global__ void k_initdeg() {
    int i = blockIdx.x * blockDim.x + threadIdx.x;
    if (i < N_NODES) d_deg[i] = 1;                // self loop
}

__global__ void k_zero() {
    int idx = blockIdx.x * blockDim.x + threadIdx.x;
    int stride = gridDim.x * blockDim.x;
    for (int i = idx; i < 4 * 2 * HID; i += stride) d_stat[i] = 0.f;
    for (int i = idx; i < N_GRAPHS * HID; i += stride) d_pool[i] = 0.f;
    for (int i = idx; i < N_GRAPHS; i += stride) d_pcnt[i] = 0.f;
}

__global__ void k_deg(const int* __restrict__ col) {
    int idx = blockIdx.x * blockDim.x + threadIdx.x;
    int stride = gridDim.x * blockDim.x;
    for (int e = idx; e < N_EDGES; e += stride)
        atomicAdd(&d_deg[col[e]], 1);
}

// scan of PADDED in-degree: pad(e) = (e + 7) & ~7
__global__ void k_scanA() {
    __shared__ int s[SCAN_B];
    int i = blockIdx.x * SCAN_B + threadIdx.x;
    int v = 0;
    if (i < N_NODES) {
        int e = d_deg[i] - 1;
        v = (e + 7) & ~7;
    }
    s[threadIdx.x] = v;
    __syncthreads();
    for (int off = 1; off < SCAN_B; off <<= 1) {
        int t = (threadIdx.x >= off) ? s[threadIdx.x - off] : 0;
        __syncthreads();
        s[threadIdx.x] += t;
        __syncthreads();
    }
    if (i < N_NODES) d_off[i] = s[threadIdx.x] - v;
    if (threadIdx.x == SCAN_B - 1) d_bsum[blockIdx.x] = s[SCAN_B - 1];
}

// fused scanB+scanC+dinv (+ sentinel dinv)
__global__ void k_scanC2() {
    __shared__ int sred[256];
    int sb = blockIdx.x >> 1;
    int v = (threadIdx.x < sb) ? d_bsum[threadIdx.x] : 0;
    sred[threadIdx.x] = v;
    __syncthreads();
#pragma unroll
    for (int off = 128; off > 0; off >>= 1) {
        if (threadIdx.x < off) sred[threadIdx.x] += sred[threadIdx.x + off];
        __syncthreads();
    }
    int pref = sred[0];
    int i = blockIdx.x * 256 + threadIdx.x;
    if (i < N_NODES) {
        int o = d_off[i] + pref;
        d_off[i] = o;
        d_cur[i] = o;
        d_dinv[i] = rsqrtf((float)d_deg[i]);
    }
    if (blockIdx.x == 0 && threadIdx.x == 0) d_dinv[N_NODES] = 0.f;
}

// write sentinel indices into the pad slots [off+e, off+pad(e))
__global__ void k_pad() {
    int i = blockIdx.x * blockDim.x + threadIdx.x;
    if (i < N_NODES) {
        int e = d_deg[i] - 1;
        int start = d_off[i];
        int padlen = (e + 7) & ~7;
        for (int k = e; k < padlen; k++) d_csr[start + k] = N_NODES;
    }
}

__global__ void k_fill(const int* __restrict__ row, const int* __restrict__ col) {
    int idx = blockIdx.x * blockDim.x + threadIdx.x;
    int stride = gridDim.x * blockDim.x;
    for (int e = idx; e < N_EDGES; e += stride) {
        int pos = atomicAdd(&d_cur[col[e]], 1);
        d_csr[pos] = row[e];
    }
}

// ---------------- GEMM ----------------
template <int KT, bool TRANS, bool DINV>
__global__ void k_gemm(const float* __restrict__ in, const float* __restrict__ W,
                       int stL, const float* __restrict__ g, const float* __restrict__ be,
                       float cnt) {
    __shared__ float sW[64 * 64];
    __shared__ float sX[64 * 68];
    __shared__ float sS[64], sT[64];
    const int tr = threadIdx.x & 15;
    const int tc = threadIdx.x >> 4;
    const int base = blockIdx.x * 64;

    if (TRANS) bn_to_smem(stL, g, be, cnt, sS, sT);

    float acc[4][4];
#pragma unroll
    for (int i = 0; i < 4; i++)
#pragma unroll
        for (int j = 0; j < 4; j++) acc[i][j] = 0.f;

    for (int kt = 0; kt < KT; kt++) {
        for (int i = threadIdx.x; i < 4096; i += 256)
            sW[i] = W[kt * 4096 + i];
        for (int i = threadIdx.x; i < 4096; i += 256) {
            int n = i >> 6, k = i & 63;
            int ng = base + n;
            float v = 0.f;
            if (ng < N_NODES) {
                if (TRANS) v = fmaxf(fmaf(d_acc[ng * 64 + k], sS[k], sT[k]), 0.f);
                else       v = in[ng * (KT * 64) + kt * 64 + k];
            }
            sX[k * 68 + n] = v;
        }
        __syncthreads();
#pragma unroll 8
        for (int kk = 0; kk < 64; kk++) {
            float4 xv = *reinterpret_cast<float4*>(&sX[kk * 68 + tr * 4]);
            float4 wv = *reinterpret_cast<float4*>(&sW[kk * 64 + tc * 4]);
            acc[0][0] = fmaf(xv.x, wv.x, acc[0][0]);
            acc[0][1] = fmaf(xv.x, wv.y, acc[0][1]);
            acc[0][2] = fmaf(xv.x, wv.z, acc[0][2]);
            acc[0][3] = fmaf(xv.x, wv.w, acc[0][3]);
            acc[1][0] = fmaf(xv.y, wv.x, acc[1][0]);
            acc[1][1] = fmaf(xv.y, wv.y, acc[1][1]);
            acc[1][2] = fmaf(xv.y, wv.z, acc[1][2]);
            acc[1][3] = fmaf(xv.y, wv.w, acc[1][3]);
            acc[2][0] = fmaf(xv.z, wv.x, acc[2][0]);
            acc[2][1] = fmaf(xv.z, wv.y, acc[2][1]);
            acc[2][2] = fmaf(xv.z, wv.z, acc[2][2]);
            acc[2][3] = fmaf(xv.z, wv.w, acc[2][3]);
            acc[3][0] = fmaf(xv.w, wv.x, acc[3][0]);
            acc[3][1] = fmaf(xv.w, wv.y, acc[3][1]);
            acc[3][2] = fmaf(xv.w, wv.z, acc[3][2]);
            acc[3][3] = fmaf(xv.w, wv.w, acc[3][3]);
        }
        __syncthreads();
    }
#pragma unroll
    for (int i = 0; i < 4; i++) {
        int n = base + tr * 4 + i;
        if (n < N_NODES) {
            float dv = DINV ? d_dinv[n] : 1.0f;
            __half2 h0 = __floats2half2_rn(acc[i][0] * dv, acc[i][1] * dv);
            __half2 h1 = __floats2half2_rn(acc[i][2] * dv, acc[i][3] * dv);
            uint2 u;
            u.x = *reinterpret_cast<unsigned*>(&h0);
            u.y = *reinterpret_cast<unsigned*>(&h1);
            *reinterpret_cast<uint2*>(&d_gh[n * 32 + tc * 2]) = u;
        }
    }
}

// ---------------- branchless padded-CSR gather-aggregate --------------------
// 4 lane-groups of 8; per 8-message step each lane issues 2 independent
// LDG.128 gathers. Sentinel rows are exact zeros. Fused BN stats.
template <bool ROWDINV>
__global__ void k_aggr4(int L) {
    __shared__ float ssum[16 * 65];
    __shared__ float ssq [16 * 65];
    const int w = threadIdx.x >> 5;
    const int lane = threadIdx.x & 31;
    const int grp = lane >> 3;
    const int sub = lane & 7;
    const int node = blockIdx.x * 16 + w;
    const uint4* __restrict__ gh4 = reinterpret_cast<const uint4*>(d_gh);

    float acc[8];
#pragma unroll
    for (int i = 0; i < 8; i++) acc[i] = 0.f;

    if (node < N_NODES) {
        const int start = d_off[node];
        const int e = d_deg[node] - 1;
        const int padlen = (e + 7) & ~7;

        for (int j = 0; j < padlen; j += 8) {
            int r0 = __ldg(&d_csr[start + j + grp]);
            int r1 = __ldg(&d_csr[start + j + 4 + grp]);
            uint4 u0 = __ldg(&gh4[r0 * 8 + sub]);
            uint4 u1 = __ldg(&gh4[r1 * 8 + sub]);
            float dm0 = 1.f, dm1 = 1.f;
            if (ROWDINV) { dm0 = __ldg(&d_dinv[r0]); dm1 = __ldg(&d_dinv[r1]); }
            float2 f;
            f = __half22float2(*reinterpret_cast<__half2*>(&u0.x));
            acc[0] = fmaf(dm0, f.x, acc[0]); acc[1] = fmaf(dm0, f.y, acc[1]);
            f = __half22float2(*reinterpret_cast<__half2*>(&u0.y));
            acc[2] = fmaf(dm0, f.x, acc[2]); acc[3] = fmaf(dm0, f.y, acc[3]);
            f = __half22float2(*reinterpret_cast<__half2*>(&u0.z));
            acc[4] = fmaf(dm0, f.x, acc[4]); acc[5] = fmaf(dm0, f.y, acc[5]);
            f = __half22float2(*reinterpret_cast<__half2*>(&u0.w));
            acc[6] = fmaf(dm0, f.x, acc[6]); acc[7] = fmaf(dm0, f.y, acc[7]);
            f = __half22float2(*reinterpret_cast<__half2*>(&u1.x));
            acc[0] = fmaf(dm1, f.x, acc[0]); acc[1] = fmaf(dm1, f.y, acc[1]);
            f = __half22float2(*reinterpret_cast<__half2*>(&u1.y));
            acc[2] = fmaf(dm1, f.x, acc[2]); acc[3] = fmaf(dm1, f.y, acc[3]);
            f = __half22float2(*reinterpret_cast<__half2*>(&u1.z));
            acc[4] = fmaf(dm1, f.x, acc[4]); acc[5] = fmaf(dm1, f.y, acc[5]);
            f = __half22float2(*reinterpret_cast<__half2*>(&u1.w));
            acc[6] = fmaf(dm1, f.x, acc[6]); acc[7] = fmaf(dm1, f.y, acc[7]);
        }

        if (grp == 0) {   // self loop
            float selfs = ROWDINV ? d_dinv[node] : 1.f;
            uint4 su = gh4[node * 8 + sub];
            float2 f;
            f = __half22float2(*reinterpret_cast<__half2*>(&su.x));
            acc[0] = fmaf(selfs, f.x, acc[0]); acc[1] = fmaf(selfs, f.y, acc[1]);
            f = __half22float2(*reinterpret_cast<__half2*>(&su.y));
            acc[2] = fmaf(selfs, f.x, acc[2]); acc[3] = fmaf(selfs, f.y, acc[3]);
            f = __half22float2(*reinterpret_cast<__half2*>(&su.z));
            acc[4] = fmaf(selfs, f.x, acc[4]); acc[5] = fmaf(selfs, f.y, acc[5]);
            f = __half22float2(*reinterpret_cast<__half2*>(&su.w));
            acc[6] = fmaf(selfs, f.x, acc[6]); acc[7] = fmaf(selfs, f.y, acc[7]);
        }
    }

    // reduce across the 4 lane groups
#pragma unroll
    for (int i = 0; i < 8; i++) acc[i] += __shfl_xor_sync(0xffffffffu, acc[i], 8);
#pragma unroll
    for (int i = 0; i < 8; i++) acc[i] += __shfl_xor_sync(0xffffffffu, acc[i], 16);

    float dv = (node < N_NODES) ? d_dinv[node] : 0.f;
#pragma unroll
    for (int i = 0; i < 8; i++) acc[i] *= dv;

    if (grp == 0) {
        if (node < N_NODES) {
            float4 o0 = make_float4(acc[0], acc[1], acc[2], acc[3]);
            float4 o1 = make_float4(acc[4], acc[5], acc[6], acc[7]);
            *reinterpret_cast<float4*>(&d_acc[node * 64 + sub * 8])     = o0;
            *reinterpret_cast<float4*>(&d_acc[node * 64 + sub * 8 + 4]) = o1;
        }
#pragma unroll
        for (int i = 0; i < 8; i++) {
            ssum[w * 65 + sub * 8 + i] = (node < N_NODES) ? acc[i] : 0.f;
            ssq [w * 65 + sub * 8 + i] = (node < N_NODES) ? acc[i] * acc[i] : 0.f;
        }
    }
    __syncthreads();
    if (threadIdx.x < 128) {
        int feat = threadIdx.x & 63;
        bool isq = threadIdx.x >= 64;
        const float* src = isq ? ssq : ssum;
        float a = 0.f;
#pragma unroll
        for (int ww = 0; ww < 16; ww++) a += src[ww * 65 + feat];
        atomicAdd(&d_stat[L * 128 + (isq ? 64 : 0) + feat], a);
    }
}

// ---------------- pooling + head ----------------
__global__ void k_pool(const int* __restrict__ batch,
                       const float* __restrict__ g, const float* __restrict__ be) {
    __shared__ float sS[64], sT[64];
    bn_to_smem(2, g, be, (float)N_NODES, sS, sT);
    int t = blockIdx.x * blockDim.x + threadIdx.x;
    int lane = t & 15;
    int n = t >> 4;
    if (n >= N_NODES) return;
    int b = batch[n];
    float4 a = *reinterpret_cast<const float4*>(&d_acc[n * 64 + lane * 4]);
    float4 z;
    z.x = fmaxf(fmaf(a.x, sS[lane * 4 + 0], sT[lane * 4 + 0]), 0.f);
    z.y = fmaxf(fmaf(a.y, sS[lane * 4 + 1], sT[lane * 4 + 1]), 0.f);
    z.z = fmaxf(fmaf(a.z, sS[lane * 4 + 2], sT[lane * 4 + 2]), 0.f);
    z.w = fmaxf(fmaf(a.w, sS[lane * 4 + 3], sT[lane * 4 + 3]), 0.f);
    red_add_v4(&d_pool[b * 64 + lane * 4], z);
    if (lane == 0) atomicAdd(&d_pcnt[b], 1.0f);
}

__global__ void k_fc1(const float* __restrict__ W1) {
    __shared__ float sp[64];
    int gidx = blockIdx.x, f = threadIdx.x;
    float cnt = fmaxf(d_pcnt[gidx], 1.f);
    sp[f] = d_pool[gidx * 64 + f] / cnt;
    __syncthreads();
    float q = 0.f;
#pragma unroll 8
    for (int k = 0; k < 64; k++)
        q = fmaf(sp[k], __ldg(&W1[k * 64 + f]), q);
    d_q[gidx * 64 + f] = q;
    atomicAdd(&d_stat[3 * 128 + f], q);
    atomicAdd(&d_stat[3 * 128 + 64 + f], q * q);
}

__global__ void k_fc2(const float* __restrict__ W2, const float* __restrict__ b2,
                      const float* __restrict__ gf, const float* __restrict__ bf,
                      float* __restrict__ out) {
    __shared__ float sS[64], sT[64];
    bn_to_smem(3, gf, bf, (float)N_GRAPHS, sS, sT);
    int g = blockIdx.x * (blockDim.x / 32) + (threadIdx.x >> 5);
    int lane = threadIdx.x & 31;
    if (g >= N_GRAPHS) return;
    float acc = 0.f;
#pragma unroll
    for (int j = 0; j < 2; j++) {
        int f = lane + 32 * j;
        float z = fmaxf(fmaf(d_q[g * 64 + f], sS[f], sT[f]), 0.f);
        acc = fmaf(z, W2[f], acc);
    }
#pragma unroll
    for (int o = 16; o > 0; o >>= 1)
        acc += __shfl_down_sync(0xffffffffu, acc, o);
    if (lane == 0) out[g] = acc + b2[0];
}

// ---------------- launch ----------------
extern "C" void kernel_launch(void* const* d_in, const int* in_sizes, int n_in,
                              void* d_out, int out_size) {
    const float* x     = (const float*)d_in[0];
    const int*   ei    = (const int*)d_in[1];
    const int*   row   = ei;
    const int*   col   = ei + N_EDGES;
    const int*   batch = (const int*)d_in[2];
    const float* Wc0 = (const float*)d_in[3];
    const float* g0  = (const float*)d_in[5];
    const float* be0 = (const float*)d_in[6];
    const float* Wc1 = (const float*)d_in[7];
    const float* g1  = (const float*)d_in[9];
    const float* be1 = (const float*)d_in[10];
    const float* Wc2 = (const float*)d_in[11];
    const float* g2  = (const float*)d_in[13];
    const float* be2 = (const float*)d_in[14];
    const float* W1  = (const float*)d_in[15];
    const float* gf  = (const float*)d_in[17];
    const float* bf  = (const float*)d_in[18];
    const float* W2  = (const float*)d_in[19];
    const float* b2  = (const float*)d_in[20];
    float* out = (float*)d_out;

    static cudaStream_t s1 = nullptr;
    static cudaEvent_t eFork = nullptr, eGemm0 = nullptr;
    if (s1 == nullptr) {
        cudaStreamCreateWithFlags(&s1, cudaStreamNonBlocking);
        cudaEventCreateWithFlags(&eFork, cudaEventDisableTiming);
        cudaEventCreateWithFlags(&eGemm0, cudaEventDisableTiming);
    }

    const int GEMM_GRID = (N_NODES + 63) / 64;              // 1563
    const int AGGR_GRID = (N_NODES + 15) / 16;              // 6250 (512 thr)
    const int POOL_GRID = (N_NODES * 16 + 255) / 256;       // 6250
    const int N256 = (N_NODES + 255) / 256;                 // 391

    // Side stream: zero stats/pool, then GEMM0 (x@Wc0, no graph dependency)
    cudaEventRecord(eFork, 0);
    cudaStreamWaitEvent(s1, eFork, 0);
    k_zero<<<512, 256, 0, s1>>>();
    k_gemm<2, false, false><<<GEMM_GRID, 256, 0, s1>>>(x, Wc0, 0, nullptr, nullptr, 1.f);
    cudaEventRecord(eGemm0, s1);

    // Critical path: padded CSR build
    k_initdeg<<<N256, 256>>>();
    k_deg <<<8192, 256>>>(col);
    k_scanA<<<NBLK, SCAN_B>>>();
    k_scanC2<<<N256, 256>>>();
    k_pad <<<N256, 256>>>();
    k_fill<<<8192, 256>>>(row, col);

    cudaStreamWaitEvent(0, eGemm0, 0);

    // layer 0 (gh = raw h fp16; dinv[row] applied in gather)
    k_aggr4<true><<<AGGR_GRID, 512>>>(0);

    // layer 1
    k_gemm<1, true, true><<<GEMM_GRID, 256>>>(x, Wc1, 0, g0, be0, (float)N_NODES);
    k_aggr4<false><<<AGGR_GRID, 512>>>(1);

    // layer 2
    k_gemm<1, true, true><<<GEMM_GRID, 256>>>(x, Wc2, 1, g1, be1, (float)N_NODES);
    k_aggr4<false><<<AGGR_GRID, 512>>>(2);

    // pooling + head
    k_pool<<<POOL_GRID, 256>>>(batch, g2, be2);
    k_fc1<<<N_GRAPHS, 64>>>(W1);
    k_fc2<<<N_GRAPHS / 8, 256>>>(W2, b2, gf, bf, out);
}

// round 8
// speedup vs baseline: 1.1988x; 1.0045x over previous
#include <cuda_runtime.h>
#include <cuda_fp16.h>

#define N_NODES 100000
#define N_EDGES 3200000
#define N_GRAPHS 4096
#define IN_DIM 128
#define HID 64
#define EPS 1e-5f

#define SCAN_B 512
#define NBLK ((N_NODES + SCAN_B - 1) / SCAN_B)   // 196
#define CSR_CAP (N_EDGES + 8 * N_NODES)

// ---------------- scratch (device globals; no allocation) ----------------
__device__ __half2 d_gh [(N_NODES + 1) * 32];    // sentinel row at N_NODES (zeros)
__device__ float   d_acc[N_NODES * HID];
__device__ int     d_deg [N_NODES];
__device__ float   d_dinv[N_NODES + 1];
__device__ int     d_off [N_NODES];
__device__ int     d_cur [N_NODES];
__device__ int     d_bsum[NBLK];
__device__ int     d_csr [CSR_CAP];
__device__ float   d_stat[4 * 2 * HID];
__device__ float   d_pool[N_GRAPHS * HID];
__device__ int     d_goff[N_GRAPHS + 1];         // graph segment offsets (batch sorted)
__device__ float   d_q   [N_GRAPHS * HID];

__device__ __forceinline__ void bn_to_smem(int L, const float* g, const float* be,
                                           float cnt, float* sS, float* sT) {
    if (threadIdx.x < 64) {
        int f = threadIdx.x;
        float mean = d_stat[L * 128 + f] / cnt;
        float var  = d_stat[L * 128 + 64 + f] / cnt - mean * mean;
        var = fmaxf(var, 0.f);
        float s = g[f] * rsqrtf(var + EPS);
        sS[f] = s;
        sT[f] = be[f] - mean * s;
    }
    __syncthreads();
}

// ---------------- setup kernels ----------------
__global__ void k_initdeg() {
    int i = blockIdx.x * blockDim.x + threadIdx.x;
    if (i < N_NODES) d_deg[i] = 1;                // self loop
}

__global__ void k_zero() {
    int i = blockIdx.x * blockDim.x + threadIdx.x;
    if (i < 4 * 2 * HID) d_stat[i] = 0.f;
}

// graph offsets by binary search over sorted batch (side stream)
__global__ void k_goff(const int* __restrict__ batch) {
    int g = blockIdx.x * blockDim.x + threadIdx.x;
    if (g > N_GRAPHS) return;
    int lo = 0, hi = N_NODES;
    while (lo < hi) {
        int mid = (lo + hi) >> 1;
        if (batch[mid] < g) lo = mid + 1; else hi = mid;
    }
    d_goff[g] = lo;
}

__global__ void k_deg(const int* __restrict__ col) {
    int idx = blockIdx.x * blockDim.x + threadIdx.x;
    int stride = gridDim.x * blockDim.x;
    for (int e = idx; e < N_EDGES; e += stride)
        atomicAdd(&d_deg[col[e]], 1);
}

// scan of PADDED in-degree: pad(e) = (e + 7) & ~7
__global__ void k_scanA() {
    __shared__ int s[SCAN_B];
    int i = blockIdx.x * SCAN_B + threadIdx.x;
    int v = 0;
    if (i < N_NODES) {
        int e = d_deg[i] - 1;
        v = (e + 7) & ~7;
    }
    s[threadIdx.x] = v;
    __syncthreads();
    for (int off = 1; off < SCAN_B; off <<= 1) {
        int t = (threadIdx.x >= off) ? s[threadIdx.x - off] : 0;
        __syncthreads();
        s[threadIdx.x] += t;
        __syncthreads();
    }
    if (i < N_NODES) d_off[i] = s[threadIdx.x] - v;
    if (threadIdx.x == SCAN_B - 1) d_bsum[blockIdx.x] = s[SCAN_B - 1];
}

// fused scanB + scanC + dinv + sentinel-pad writes
__global__ void k_scanC2() {
    __shared__ int sred[256];
    int sb = blockIdx.x >> 1;
    int v = (threadIdx.x < sb) ? d_bsum[threadIdx.x] : 0;
    sred[threadIdx.x] = v;
    __syncthreads();
#pragma unroll
    for (int off = 128; off > 0; off >>= 1) {
        if (threadIdx.x < off) sred[threadIdx.x] += sred[threadIdx.x + off];
        __syncthreads();
    }
    int pref = sred[0];
    int i = blockIdx.x * 256 + threadIdx.x;
    if (i < N_NODES) {
        int o = d_off[i] + pref;
        int e = d_deg[i] - 1;
        d_off[i] = o;
        d_cur[i] = o;
        d_dinv[i] = rsqrtf((float)(e + 1));
        int padlen = (e + 7) & ~7;
        for (int k = e; k < padlen; k++) d_csr[o + k] = N_NODES;
    }
    if (blockIdx.x == 0 && threadIdx.x == 0) d_dinv[N_NODES] = 0.f;
}

__global__ void k_fill(const int* __restrict__ row, const int* __restrict__ col) {
    int idx = blockIdx.x * blockDim.x + threadIdx.x;
    int stride = gridDim.x * blockDim.x;
    for (int e = idx; e < N_EDGES; e += stride) {
        int pos = atomicAdd(&d_cur[col[e]], 1);
        d_csr[pos] = row[e];
    }
}

// ---------------- GEMM ----------------
template <int KT, bool TRANS, bool DINV>
__global__ void k_gemm(const float* __restrict__ in, const float* __restrict__ W,
                       int stL, const float* __restrict__ g, const float* __restrict__ be,
                       float cnt) {
    __shared__ float sW[64 * 64];
    __shared__ float sX[64 * 68];
    __shared__ float sS[64], sT[64];
    const int tr = threadIdx.x & 15;
    const int tc = threadIdx.x >> 4;
    const int base = blockIdx.x * 64;

    if (TRANS) bn_to_smem(stL, g, be, cnt, sS, sT);

    float acc[4][4];
#pragma unroll
    for (int i = 0; i < 4; i++)
#pragma unroll
        for (int j = 0; j < 4; j++) acc[i][j] = 0.f;

    for (int kt = 0; kt < KT; kt++) {
        for (int i = threadIdx.x; i < 4096; i += 256)
            sW[i] = W[kt * 4096 + i];
        for (int i = threadIdx.x; i < 4096; i += 256) {
            int n = i >> 6, k = i & 63;
            int ng = base + n;
            float v = 0.f;
            if (ng < N_NODES) {
                if (TRANS) v = fmaxf(fmaf(d_acc[ng * 64 + k], sS[k], sT[k]), 0.f);
                else       v = in[ng * (KT * 64) + kt * 64 + k];
            }
            sX[k * 68 + n] = v;
        }
        __syncthreads();
#pragma unroll 8
        for (int kk = 0; kk < 64; kk++) {
            float4 xv = *reinterpret_cast<float4*>(&sX[kk * 68 + tr * 4]);
            float4 wv = *reinterpret_cast<float4*>(&sW[kk * 64 + tc * 4]);
            acc[0][0] = fmaf(xv.x, wv.x, acc[0][0]);
            acc[0][1] = fmaf(xv.x, wv.y, acc[0][1]);
            acc[0][2] = fmaf(xv.x, wv.z, acc[0][2]);
            acc[0][3] = fmaf(xv.x, wv.w, acc[0][3]);
            acc[1][0] = fmaf(xv.y, wv.x, acc[1][0]);
            acc[1][1] = fmaf(xv.y, wv.y, acc[1][1]);
            acc[1][2] = fmaf(xv.y, wv.z, acc[1][2]);
            acc[1][3] = fmaf(xv.y, wv.w, acc[1][3]);
            acc[2][0] = fmaf(xv.z, wv.x, acc[2][0]);
            acc[2][1] = fmaf(xv.z, wv.y, acc[2][1]);
            acc[2][2] = fmaf(xv.z, wv.z, acc[2][2]);
            acc[2][3] = fmaf(xv.z, wv.w, acc[2][3]);
            acc[3][0] = fmaf(xv.w, wv.x, acc[3][0]);
            acc[3][1] = fmaf(xv.w, wv.y, acc[3][1]);
            acc[3][2] = fmaf(xv.w, wv.z, acc[3][2]);
            acc[3][3] = fmaf(xv.w, wv.w, acc[3][3]);
        }
        __syncthreads();
    }
#pragma unroll
    for (int i = 0; i < 4; i++) {
        int n = base + tr * 4 + i;
        if (n < N_NODES) {
            float dv = DINV ? d_dinv[n] : 1.0f;
            __half2 h0 = __floats2half2_rn(acc[i][0] * dv, acc[i][1] * dv);
            __half2 h1 = __floats2half2_rn(acc[i][2] * dv, acc[i][3] * dv);
            uint2 u;
            u.x = *reinterpret_cast<unsigned*>(&h0);
            u.y = *reinterpret_cast<unsigned*>(&h1);
            *reinterpret_cast<uint2*>(&d_gh[n * 32 + tc * 2]) = u;
        }
    }
}

// ---------------- branchless padded-CSR gather-aggregate --------------------
template <bool ROWDINV>
__global__ void k_aggr4(int L) {
    __shared__ float ssum[16 * 65];
    __shared__ float ssq [16 * 65];
    const int w = threadIdx.x >> 5;
    const int lane = threadIdx.x & 31;
    const int grp = lane >> 3;
    const int sub = lane & 7;
    const int node = blockIdx.x * 16 + w;
    const uint4* __restrict__ gh4 = reinterpret_cast<const uint4*>(d_gh);

    float acc[8];
#pragma unroll
    for (int i = 0; i < 8; i++) acc[i] = 0.f;

    if (node < N_NODES) {
        const int start = d_off[node];
        const int e = d_deg[node] - 1;
        const int padlen = (e + 7) & ~7;

        for (int j = 0; j < padlen; j += 8) {
            int r0 = __ldg(&d_csr[start + j + grp]);
            int r1 = __ldg(&d_csr[start + j + 4 + grp]);
            uint4 u0 = __ldg(&gh4[r0 * 8 + sub]);
            uint4 u1 = __ldg(&gh4[r1 * 8 + sub]);
            float dm0 = 1.f, dm1 = 1.f;
            if (ROWDINV) { dm0 = __ldg(&d_dinv[r0]); dm1 = __ldg(&d_dinv[r1]); }
            float2 f;
            f = __half22float2(*reinterpret_cast<__half2*>(&u0.x));
            acc[0] = fmaf(dm0, f.x, acc[0]); acc[1] = fmaf(dm0, f.y, acc[1]);
            f = __half22float2(*reinterpret_cast<__half2*>(&u0.y));
            acc[2] = fmaf(dm0, f.x, acc[2]); acc[3] = fmaf(dm0, f.y, acc[3]);
            f = __half22float2(*reinterpret_cast<__half2*>(&u0.z));
            acc[4] = fmaf(dm0, f.x, acc[4]); acc[5] = fmaf(dm0, f.y, acc[5]);
            f = __half22float2(*reinterpret_cast<__half2*>(&u0.w));
            acc[6] = fmaf(dm0, f.x, acc[6]); acc[7] = fmaf(dm0, f.y, acc[7]);
            f = __half22float2(*reinterpret_cast<__half2*>(&u1.x));
            acc[0] = fmaf(dm1, f.x, acc[0]); acc[1] = fmaf(dm1, f.y, acc[1]);
            f = __half22float2(*reinterpret_cast<__half2*>(&u1.y));
            acc[2] = fmaf(dm1, f.x, acc[2]); acc[3] = fmaf(dm1, f.y, acc[3]);
            f = __half22float2(*reinterpret_cast<__half2*>(&u1.z));
            acc[4] = fmaf(dm1, f.x, acc[4]); acc[5] = fmaf(dm1, f.y, acc[5]);
            f = __half22float2(*reinterpret_cast<__half2*>(&u1.w));
            acc[6] = fmaf(dm1, f.x, acc[6]); acc[7] = fmaf(dm1, f.y, acc[7]);
        }

        if (grp == 0) {   // self loop
            float selfs = ROWDINV ? d_dinv[node] : 1.f;
            uint4 su = gh4[node * 8 + sub];
            float2 f;
            f = __half22float2(*reinterpret_cast<__half2*>(&su.x));
            acc[0] = fmaf(selfs, f.x, acc[0]); acc[1] = fmaf(selfs, f.y, acc[1]);
            f = __half22float2(*reinterpret_cast<__half2*>(&su.y));
            acc[2] = fmaf(selfs, f.x, acc[2]); acc[3] = fmaf(selfs, f.y, acc[3]);
            f = __half22float2(*reinterpret_cast<__half2*>(&su.z));
            acc[4] = fmaf(selfs, f.x, acc[4]); acc[5] = fmaf(selfs, f.y, acc[5]);
            f = __half22float2(*reinterpret_cast<__half2*>(&su.w));
            acc[6] = fmaf(selfs, f.x, acc[6]); acc[7] = fmaf(selfs, f.y, acc[7]);
        }
    }

#pragma unroll
    for (int i = 0; i < 8; i++) acc[i] += __shfl_xor_sync(0xffffffffu, acc[i], 8);
#pragma unroll
    for (int i = 0; i < 8; i++) acc[i] += __shfl_xor_sync(0xffffffffu, acc[i], 16);

    float dv = (node < N_NODES) ? d_dinv[node] : 0.f;
#pragma unroll
    for (int i = 0; i < 8; i++) acc[i] *= dv;

    if (grp == 0) {
        if (node < N_NODES) {
            float4 o0 = make_float4(acc[0], acc[1], acc[2], acc[3]);
            float4 o1 = make_float4(acc[4], acc[5], acc[6], acc[7]);
            *reinterpret_cast<float4*>(&d_acc[node * 64 + sub * 8])     = o0;
            *reinterpret_cast<float4*>(&d_acc[node * 64 + sub * 8 + 4]) = o1;
        }
#pragma unroll
        for (int i = 0; i < 8; i++) {
            ssum[w * 65 + sub * 8 + i] = (node < N_NODES) ? acc[i] : 0.f;
            ssq [w * 65 + sub * 8 + i] = (node < N_NODES) ? acc[i] * acc[i] : 0.f;
        }
    }
    __syncthreads();
    if (threadIdx.x < 128) {
        int feat = threadIdx.x & 63;
        bool isq = threadIdx.x >= 64;
        const float* src = isq ? ssq : ssum;
        float a = 0.f;
#pragma unroll
        for (int ww = 0; ww < 16; ww++) a += src[ww * 65 + feat];
        atomicAdd(&d_stat[L * 128 + (isq ? 64 : 0) + feat], a);
    }
}

// ---------------- pooling (sorted batch: one warp per graph, no atomics) ----
__global__ void k_pool2(const float* __restrict__ g, const float* __restrict__ be) {
    __shared__ float sS[64], sT[64];
    bn_to_smem(2, g, be, (float)N_NODES, sS, sT);
    const int w = threadIdx.x >> 5;          // 8 warps/block
    const int lane = threadIdx.x & 31;
    const int gidx = blockIdx.x * 8 + w;
    if (gidx >= N_GRAPHS) return;
    const int s = d_goff[gidx];
    const int e = d_goff[gidx + 1];
    const int half = lane >> 4;              // 0/1: two rows in parallel
    const int chunk = lane & 15;             // float4 chunk within row

    float4 a = make_float4(0.f, 0.f, 0.f, 0.f);
    for (int n = s + half; n < e; n += 2) {
        float4 v = *reinterpret_cast<const float4*>(&d_acc[n * 64 + chunk * 4]);
        a.x += fmaxf(fmaf(v.x, sS[chunk * 4 + 0], sT[chunk * 4 + 0]), 0.f);
        a.y += fmaxf(fmaf(v.y, sS[chunk * 4 + 1], sT[chunk * 4 + 1]), 0.f);
        a.z += fmaxf(fmaf(v.z, sS[chunk * 4 + 2], sT[chunk * 4 + 2]), 0.f);
        a.w += fmaxf(fmaf(v.w, sS[chunk * 4 + 3], sT[chunk * 4 + 3]), 0.f);
    }
    a.x += __shfl_xor_sync(0xffffffffu, a.x, 16);
    a.y += __shfl_xor_sync(0xffffffffu, a.y, 16);
    a.z += __shfl_xor_sync(0xffffffffu, a.z, 16);
    a.w += __shfl_xor_sync(0xffffffffu, a.w, 16);
    if (half == 0) {
        float inv = 1.0f / fmaxf((float)(e - s), 1.0f);
        float4 o = make_float4(a.x * inv, a.y * inv, a.z * inv, a.w * inv);
        *reinterpret_cast<float4*>(&d_pool[gidx * 64 + chunk * 4]) = o;
    }
}

// ---------------- fc1: 8 graphs per block, block-reduced stats --------------
__global__ void k_fc1(const float* __restrict__ W1) {
    __shared__ float sp[8 * 64];
    __shared__ float sq1[8 * 65], sq2[8 * 65];
    const int grp = threadIdx.x >> 6;        // 0..7
    const int f = threadIdx.x & 63;
    const int gidx = blockIdx.x * 8 + grp;
    sp[grp * 64 + f] = d_pool[gidx * 64 + f];
    __syncthreads();
    float q = 0.f;
    const float* pv = &sp[grp * 64];
#pragma unroll 8
    for (int k = 0; k < 64; k++)
        q = fmaf(pv[k], __ldg(&W1[k * 64 + f]), q);
    d_q[gidx * 64 + f] = q;
    sq1[grp * 65 + f] = q;
    sq2[grp * 65 + f] = q * q;
    __syncthreads();
    if (threadIdx.x < 128) {
        int feat = threadIdx.x & 63;
        bool isq = threadIdx.x >= 64;
        const float* src = isq ? sq2 : sq1;
        float a = 0.f;
#pragma unroll
        for (int gg = 0; gg < 8; gg++) a += src[gg * 65 + feat];
        atomicAdd(&d_stat[3 * 128 + (isq ? 64 : 0) + feat], a);
    }
}

__global__ void k_fc2(const float* __restrict__ W2, const float* __restrict__ b2,
                      const float* __restrict__ gf, const float* __restrict__ bf,
                      float* __restrict__ out) {
    __shared__ float sS[64], sT[64];
    bn_to_smem(3, gf, bf, (float)N_GRAPHS, sS, sT);
    int g = blockIdx.x * (blockDim.x / 32) + (threadIdx.x >> 5);
    int lane = threadIdx.x & 31;
    if (g >= N_GRAPHS) return;
    float acc = 0.f;
#pragma unroll
    for (int j = 0; j < 2; j++) {
        int f = lane + 32 * j;
        float z = fmaxf(fmaf(d_q[g * 64 + f], sS[f], sT[f]), 0.f);
        acc = fmaf(z, W2[f], acc);
    }
#pragma unroll
    for (int o = 16; o > 0; o >>= 1)
        acc += __shfl_down_sync(0xffffffffu, acc, o);
    if (lane == 0) out[g] = acc + b2[0];
}

// ---------------- launch ----------------
extern "C" void kernel_launch(void* const* d_in, const int* in_sizes, int n_in,
                              void* d_out, int out_size) {
    const float* x     = (const float*)d_in[0];
    const int*   ei    = (const int*)d_in[1];
    const int*   row   = ei;
    const int*   col   = ei + N_EDGES;
    const int*   batch = (const int*)d_in[2];
    const float* Wc0 = (const float*)d_in[3];
    const float* g0  = (const float*)d_in[5];
    const float* be0 = (const float*)d_in[6];
    const float* Wc1 = (const float*)d_in[7];
    const float* g1  = (const float*)d_in[9];
    const float* be1 = (const float*)d_in[10];
    const float* Wc2 = (const float*)d_in[11];
    const float* g2  = (const float*)d_in[13];
    const float* be2 = (const float*)d_in[14];
    const float* W1  = (const float*)d_in[15];
    const float* gf  = (const float*)d_in[17];
    const float* bf  = (const float*)d_in[18];
    const float* W2  = (const float*)d_in[19];
    const float* b2  = (const float*)d_in[20];
    float* out = (float*)d_out;

    static cudaStream_t s1 = nullptr;
    static cudaEvent_t eFork = nullptr, eGemm0 = nullptr;
    if (s1 == nullptr) {
        cudaStreamCreateWithFlags(&s1, cudaStreamNonBlocking);
        cudaEventCreateWithFlags(&eFork, cudaEventDisableTiming);
        cudaEventCreateWithFlags(&eGemm0, cudaEventDisableTiming);
    }

    const int GEMM_GRID = (N_NODES + 63) / 64;              // 1563
    const int AGGR_GRID = (N_NODES + 15) / 16;              // 6250
    const int N256 = (N_NODES + 255) / 256;                 // 391

    // Side stream: zero stats, graph offsets, GEMM0 (all graph-structure-free
    // except goff which only needs batch)
    cudaEventRecord(eFork, 0);
    cudaStreamWaitEvent(s1, eFork, 0);
    k_zero<<<2, 256, 0, s1>>>();
    k_goff<<<(N_GRAPHS + 256) / 256, 256, 0, s1>>>(batch);
    k_gemm<2, false, false><<<GEMM_GRID, 256, 0, s1>>>(x, Wc0, 0, nullptr, nullptr, 1.f);
    cudaEventRecord(eGemm0, s1);

    // Critical path: padded CSR build (pad fused into scanC2)
    k_initdeg<<<N256, 256>>>();
    k_deg <<<8192, 256>>>(col);
    k_scanA<<<NBLK, SCAN_B>>>();
    k_scanC2<<<N256, 256>>>();
    k_fill<<<8192, 256>>>(row, col);

    cudaStreamWaitEvent(0, eGemm0, 0);

    // layer 0
    k_aggr4<true><<<AGGR_GRID, 512>>>(0);
    // layer 1
    k_gemm<1, true, true><<<GEMM_GRID, 256>>>(x, Wc1, 0, g0, be0, (float)N_NODES);
    k_aggr4<false><<<AGGR_GRID, 512>>>(1);
    // layer 2
    k_gemm<1, true, true><<<GEMM_GRID, 256>>>(x, Wc2, 1, g1, be1, (float)N_NODES);
    k_aggr4<false><<<AGGR_GRID, 512>>>(2);

    // pooling + head
    k_pool2<<<N_GRAPHS / 8, 256>>>(g2, be2);
    k_fc1<<<N_GRAPHS / 8, 512>>>(W1);
    k_fc2<<<N_GRAPHS / 8, 256>>>(W2, b2, gf, bf, out);
}